// round 6
// baseline (speedup 1.0000x reference)
#include <cuda_runtime.h>
#include <cuda_fp16.h>
#include <math.h>
#include <stdint.h>

#define NN 8192
#define F  256
#define ALPHA_C 0.2f

// ---------------- scratch ----------------
__device__ float    g_Wh[NN * F];              // fp32 Wh [i][n]
__device__ uint32_t g_WhBh[NN / 32 * F * 16];  // fp16 Wh, B-fragment order
__device__ float    g_ssrc[NN];
__device__ float    g_sdst[NN];
__device__ float    g_E0[NN];
__device__ float    g_E1[NN];
__device__ float    g_c0[NN];
__device__ float    g_c1[NN];
__device__ float    g_pmax[32];

// ---------------- helpers ----------------
__device__ __forceinline__ void mma_f16(float* d, const uint32_t* a, uint32_t b0, uint32_t b1) {
    asm volatile(
        "mma.sync.aligned.m16n8k16.row.col.f32.f16.f16.f32 "
        "{%0,%1,%2,%3}, {%4,%5,%6,%7}, {%8,%9}, {%0,%1,%2,%3};\n"
        : "+f"(d[0]), "+f"(d[1]), "+f"(d[2]), "+f"(d[3])
        : "r"(a[0]), "r"(a[1]), "r"(a[2]), "r"(a[3]), "r"(b0), "r"(b1));
}

// ---------------- K1: Wh = X @ W^T (fp32), BM=64 x BN=128 ----------------
__global__ void __launch_bounds__(256) k1_wh(const float* __restrict__ X,
                                             const float* __restrict__ W) {
    __shared__ float Xs[16][64];
    __shared__ float Ws[16][128];
    const int tid = threadIdx.x;
    const int i0  = blockIdx.x * 64;
    const int nb  = blockIdx.y * 128;
    const int ty  = tid >> 5, tx = tid & 31;
    const int r   = tid & 63, kg = tid >> 6;
    const int o   = tid & 127, kh = tid >> 7;

    float acc[8][4];
#pragma unroll
    for (int m = 0; m < 8; m++)
#pragma unroll
        for (int n = 0; n < 4; n++) acc[m][n] = 0.f;

    for (int f0 = 0; f0 < F; f0 += 16) {
        float4 xv = *(const float4*)&X[(size_t)(i0 + r) * F + f0 + kg * 4];
        Xs[kg * 4 + 0][r] = xv.x;
        Xs[kg * 4 + 1][r] = xv.y;
        Xs[kg * 4 + 2][r] = xv.z;
        Xs[kg * 4 + 3][r] = xv.w;
        const float* wp = &W[(size_t)(nb + o) * F + f0 + kh * 8];
        float4 w0 = *(const float4*)(wp + 0);
        float4 w1 = *(const float4*)(wp + 4);
        Ws[kh * 8 + 0][o] = w0.x;  Ws[kh * 8 + 1][o] = w0.y;
        Ws[kh * 8 + 2][o] = w0.z;  Ws[kh * 8 + 3][o] = w0.w;
        Ws[kh * 8 + 4][o] = w1.x;  Ws[kh * 8 + 5][o] = w1.y;
        Ws[kh * 8 + 6][o] = w1.z;  Ws[kh * 8 + 7][o] = w1.w;
        __syncthreads();
#pragma unroll
        for (int kk = 0; kk < 16; kk++) {
            float av[8], bv[4];
            *(float4*)(av + 0) = *(const float4*)&Xs[kk][ty * 8 + 0];
            *(float4*)(av + 4) = *(const float4*)&Xs[kk][ty * 8 + 4];
            *(float4*)(bv + 0) = *(const float4*)&Ws[kk][tx * 4];
#pragma unroll
            for (int m = 0; m < 8; m++)
#pragma unroll
                for (int n = 0; n < 4; n++) acc[m][n] += av[m] * bv[n];
        }
        __syncthreads();
    }
#pragma unroll
    for (int m = 0; m < 8; m++) {
        int row = i0 + ty * 8 + m;
        *(float4*)&g_Wh[(size_t)row * F + nb + tx * 4] =
            make_float4(acc[m][0], acc[m][1], acc[m][2], acc[m][3]);
    }
}

// ---------------- K1b: pack Wh -> fp16 B-fragment order ----------------
__global__ void __launch_bounds__(256) k1b_pack() {
    __shared__ float sm[32][33];
    const int j0 = blockIdx.x * 32;
    const int n0 = blockIdx.y * 32;
    const int x = threadIdx.x, y = threadIdx.y;   // 32 x 8
#pragma unroll
    for (int q = 0; q < 4; q++)
        sm[y + q * 8][x] = g_Wh[(size_t)(j0 + y + q * 8) * F + n0 + x];
    __syncthreads();
    const int pi  = x & 15;
    const int nbs = x >> 4;
    const int t   = pi >> 2, ks = (pi >> 1) & 1, hi8 = pi & 1;
    const int jl  = ks * 16 + 2 * t + 8 * hi8;
#pragma unroll
    for (int q = 0; q < 2; q++) {
        int nl = y + nbs * 8 + q * 16;
        __half2 h = __floats2half2_rn(sm[jl][nl], sm[jl + 1][nl]);
        g_WhBh[(size_t)(j0 >> 5) * (F * 16) + (size_t)(n0 + nl) * 16 + pi] =
            *(const uint32_t*)&h;
    }
}

// ---------------- K2: scores ----------------
__global__ void __launch_bounds__(256) k2_scores(const float* __restrict__ r) {
    const int gwarp = (blockIdx.x * blockDim.x + threadIdx.x) >> 5;
    const int lane  = threadIdx.x & 31;
    if (gwarp >= NN) return;
    const float* row = &g_Wh[(size_t)gwarp * F];
    float ss = 0.f, sd = 0.f;
#pragma unroll
    for (int q = 0; q < 8; q++) {
        int k = lane + q * 32;
        float v = row[k];
        ss += v * __ldg(&r[k]);
        sd += v * __ldg(&r[F + k]);
    }
#pragma unroll
    for (int o = 16; o > 0; o >>= 1) {
        ss += __shfl_xor_sync(0xffffffffu, ss, o);
        sd += __shfl_xor_sync(0xffffffffu, sd, o);
    }
    if (lane == 0) {
        g_ssrc[gwarp] = ss;
        g_sdst[gwarp] = sd;
    }
}

// ---------------- K3a: partial max of sdst (32 blocks) ----------------
__global__ void __launch_bounds__(256) k3a_pmax() {
    __shared__ float red[256];
    const int t = threadIdx.x;
    red[t] = g_sdst[blockIdx.x * 256 + t];
    __syncthreads();
    for (int s = 128; s > 0; s >>= 1) {
        if (t < s) red[t] = fmaxf(red[t], red[t + s]);
        __syncthreads();
    }
    if (t == 0) g_pmax[blockIdx.x] = red[0];
}

// ---------------- K3b: finish max + stable exp tables ----------------
__global__ void __launch_bounds__(256) k3b_tables() {
    __shared__ float Msh;
    const int t = threadIdx.x;
    if (t < 32) {
        float m = g_pmax[t];
#pragma unroll
        for (int o = 16; o > 0; o >>= 1) m = fmaxf(m, __shfl_xor_sync(0xffffffffu, m, o));
        if (t == 0) Msh = m;
    }
    __syncthreads();
    const float M = Msh;
    const int i = blockIdx.x * 256 + t;
    const float sd = g_sdst[i];
    const float si = g_ssrc[i];
    g_E0[i] = expf(sd - M);
    g_E1[i] = expf(ALPHA_C * (sd - M));
    float u  = si + M;
    float mi = (u >= 0.f) ? u : ALPHA_C * u;
    g_c0[i] = expf(u - mi);
    g_c1[i] = expf(ALPHA_C * u - mi);
}

// ---------------- K4: fp16 mma, pipelined builder-under-MMA ----------------
// smem: B 2 x 16384 @0 ; fragA 2 x 4096 @32768 ; zsh 512f @40960 ; zinv 64f @43008
#define BBUF     16384
#define FRAG_OFF 32768
#define FRAGBUF  4096
#define ZSH_OFF  40960
#define ZINV_OFF 43008
#define K4_SMEM  43264

__global__ void __launch_bounds__(512) k4_mma(const int* __restrict__ A,
                                              float* __restrict__ out) {
    extern __shared__ char smem[];
    const int tid  = threadIdx.x, lane = tid & 31, warp = tid >> 5;
    const int i0 = blockIdx.x * 64;
    const int g = lane >> 2, t = lane & 3;
    const int my = warp >> 2, wx = warp & 3;

    // ---- builder mapping: row r, 4 j's at offset jo within each 32-chunk ----
    const int r  = tid >> 3;
    const int jo = (tid & 7) * 4;
    const float c0 = g_c0[i0 + r];
    const float c1 = g_c1[i0 + r];
    const int4* arow = (const int4*)(A + (size_t)(i0 + r) * NN) + (jo >> 2);
    const int ks_b = jo >> 4, kk = jo & 15;
    const int tA = (kk & 7) >> 1, hi = kk >> 3;
    char* fb0 = smem + FRAG_OFF +
                ((((r >> 4) * 2 + ks_b) * 32 + (r & 7) * 4 + tA) * 16 + hi * 8 + ((r >> 3) & 1) * 4);
    float zp = 0.f;

    // ---- B loader mapping ----
    const uint32_t* bsrc = g_WhBh + (size_t)(tid >> 1) * 16 + (size_t)(tid & 1) * 8;
    const uint32_t bdst = (uint32_t)__cvta_generic_to_shared(smem) + (tid >> 1) * 64 + (tid & 1) * 32;

    float acc[8][4];
#pragma unroll
    for (int u = 0; u < 8; u++)
#pragma unroll
        for (int q = 0; q < 4; q++) acc[u][q] = 0.f;

    // ---- builder lambda-ish macro ----
#define BUILD_CHUNK(CIDX, MASK, SBUF) do {                                     \
        const int jj = (CIDX) * 32 + jo;                                       \
        float4 e0 = *(const float4*)(g_E0 + jj);                               \
        float4 e1 = *(const float4*)(g_E1 + jj);                               \
        float w0 = fmaxf(c0 * e0.x, c1 * e1.x);                                \
        float w1 = fmaxf(c0 * e0.y, c1 * e1.y);                                \
        float w2 = fmaxf(c0 * e0.z, c1 * e1.z);                                \
        float w3 = fmaxf(c0 * e0.w, c1 * e1.w);                                \
        __half2 p0 = __floats2half2_rn(w0, w1);                                \
        __half2 p1 = __floats2half2_rn(w2, w3);                                \
        uint32_t m0 = ((MASK).x ? 0x0000FFFFu : 0u) | ((MASK).y ? 0xFFFF0000u : 0u); \
        uint32_t m1 = ((MASK).z ? 0x0000FFFFu : 0u) | ((MASK).w ? 0xFFFF0000u : 0u); \
        uint32_t b0 = (*(const uint32_t*)&p0) & m0;                            \
        uint32_t b1 = (*(const uint32_t*)&p1) & m1;                            \
        char* fb = fb0 + (SBUF) * FRAGBUF;                                     \
        *(uint32_t*)(fb)      = b0;                                            \
        *(uint32_t*)(fb + 16) = b1;                                            \
        float2 z0 = __half22float2(*(const __half2*)&b0);                      \
        float2 z1 = __half22float2(*(const __half2*)&b1);                      \
        zp += (z0.x + z0.y) + (z1.x + z1.y);                                   \
    } while (0)

    // ---- prologue: build chunk 0, load B0, prefetch A-mask chunk 1 ----
    {
        int4 a0 = __ldg(arow);
        BUILD_CHUNK(0, a0, 0);
        asm volatile("cp.async.cg.shared.global [%0], [%1], 16;" :: "r"(bdst), "l"(bsrc));
        asm volatile("cp.async.cg.shared.global [%0], [%1], 16;" :: "r"(bdst + 16), "l"(bsrc + 4));
        asm volatile("cp.async.commit_group;");
    }
    int4 cA = __ldg(arow + 8);

    for (int it = 0; it < NN / 32; ++it) {
        const int s = it & 1;

        asm volatile("cp.async.wait_group 0;");
        __syncthreads();

        // ---- MMA chunk it from buffers s ----
        {
            const char* bb = smem + s * BBUF;
            const char* fa = smem + FRAG_OFF + s * FRAGBUF;
            uint4 aq0 = *(const uint4*)(fa + ((my * 2 + 0) * 32 + lane) * 16);
            uint4 aq1 = *(const uint4*)(fa + ((my * 2 + 1) * 32 + lane) * 16);
#pragma unroll
            for (int u = 0; u < 8; u++) {
                uint4 bq = *(const uint4*)(bb + (wx * 64 + u * 8 + g) * 64 + t * 16);
                mma_f16(acc[u], (const uint32_t*)&aq0, bq.x, bq.y);
                mma_f16(acc[u], (const uint32_t*)&aq1, bq.z, bq.w);
            }
        }

        // ---- build chunk it+1 into buffers s^1, prefetch A-mask, issue B ----
        if (it < NN / 32 - 1) {
            BUILD_CHUNK(it + 1, cA, s ^ 1);
            if (it < NN / 32 - 2) cA = __ldg(arow + (it + 2) * 8);
            const uint32_t* src = bsrc + (size_t)(it + 1) * 4096;
            uint32_t dst = bdst + (s ^ 1) * BBUF;
            asm volatile("cp.async.cg.shared.global [%0], [%1], 16;" :: "r"(dst), "l"(src));
            asm volatile("cp.async.cg.shared.global [%0], [%1], 16;" :: "r"(dst + 16), "l"(src + 4));
            asm volatile("cp.async.commit_group;");
        }
    }
#undef BUILD_CHUNK

    // ---- Z reduce (deterministic) ----
    float* zsh  = (float*)(smem + ZSH_OFF);
    float* zinv = (float*)(smem + ZINV_OFF);
    __syncthreads();
    zsh[tid] = zp;
    __syncthreads();
    if (tid < 64) {
        const float* p = zsh + tid * 8;
        float z = ((p[0] + p[1]) + (p[2] + p[3])) + ((p[4] + p[5]) + (p[6] + p[7]));
        zinv[tid] = 1.0f / z;
    }
    __syncthreads();

    // ---- epilogue: /Z, exact GELU, store ----
    const int rr = my * 16 + g;
    const float zi0 = zinv[rr];
    const float zi1 = zinv[rr + 8];
#pragma unroll
    for (int u = 0; u < 8; u++) {
        int col = wx * 64 + u * 8 + t * 2;
        float x0 = acc[u][0] * zi0;
        float x1 = acc[u][1] * zi0;
        float x2 = acc[u][2] * zi1;
        float x3 = acc[u][3] * zi1;
        float g0 = 0.5f * x0 * (1.0f + erff(x0 * 0.70710678118654752f));
        float g1 = 0.5f * x1 * (1.0f + erff(x1 * 0.70710678118654752f));
        float g2 = 0.5f * x2 * (1.0f + erff(x2 * 0.70710678118654752f));
        float g3 = 0.5f * x3 * (1.0f + erff(x3 * 0.70710678118654752f));
        *(float2*)&out[(size_t)(i0 + rr) * F + col]     = make_float2(g0, g1);
        *(float2*)&out[(size_t)(i0 + rr + 8) * F + col] = make_float2(g2, g3);
    }
}

// ---------------- launch ----------------
extern "C" void kernel_launch(void* const* d_in, const int* in_sizes, int n_in,
                              void* d_out, int out_size) {
    (void)in_sizes; (void)n_in; (void)out_size;
    const float* X = (const float*)d_in[0];
    const int*   A = (const int*)d_in[1];
    const float* W = (const float*)d_in[2];
    const float* r = (const float*)d_in[3];
    float* out = (float*)d_out;

    cudaFuncSetAttribute(k4_mma, cudaFuncAttributeMaxDynamicSharedMemorySize, K4_SMEM);

    k1_wh<<<dim3(NN / 64, 2), 256>>>(X, W);
    k1b_pack<<<dim3(NN / 32, F / 32), dim3(32, 8)>>>();
    k2_scores<<<(NN * 32) / 256, 256>>>(r);
    k3a_pmax<<<32, 256>>>();
    k3b_tables<<<NN / 256, 256>>>();
    k4_mma<<<NN / 64, 512, K4_SMEM>>>(A, out);
}

// round 7
// speedup vs baseline: 1.1590x; 1.1590x over previous
#include <cuda_runtime.h>
#include <cuda_fp16.h>
#include <math.h>
#include <stdint.h>

#define NN 8192
#define F  256
#define ALPHA_C 0.2f

// ---------------- scratch ----------------
__device__ float    g_Wh[NN * F];              // fp32 Wh [i][n]
__device__ uint32_t g_WhBh[NN / 32 * F * 16];  // fp16 Wh, B-fragment order
__device__ float    g_ssrc[NN];
__device__ float    g_sdst[NN];
__device__ float    g_E0[NN];
__device__ float    g_E1[NN];
__device__ float    g_c0[NN];
__device__ float    g_c1[NN];
__device__ float    g_pmax[32];

// ---------------- helpers ----------------
__device__ __forceinline__ void mma_f16(float* d, const uint32_t* a, uint32_t b0, uint32_t b1) {
    asm volatile(
        "mma.sync.aligned.m16n8k16.row.col.f32.f16.f16.f32 "
        "{%0,%1,%2,%3}, {%4,%5,%6,%7}, {%8,%9}, {%0,%1,%2,%3};\n"
        : "+f"(d[0]), "+f"(d[1]), "+f"(d[2]), "+f"(d[3])
        : "r"(a[0]), "r"(a[1]), "r"(a[2]), "r"(a[3]), "r"(b0), "r"(b1));
}

// ---------------- K1: Wh = X @ W^T (fp32), BM=64 x BN=128 ----------------
__global__ void __launch_bounds__(256) k1_wh(const float* __restrict__ X,
                                             const float* __restrict__ W) {
    __shared__ float Xs[16][64];
    __shared__ float Ws[16][128];
    const int tid = threadIdx.x;
    const int i0  = blockIdx.x * 64;
    const int nb  = blockIdx.y * 128;
    const int ty  = tid >> 5, tx = tid & 31;
    const int r   = tid & 63, kg = tid >> 6;
    const int o   = tid & 127, kh = tid >> 7;

    float acc[8][4];
#pragma unroll
    for (int m = 0; m < 8; m++)
#pragma unroll
        for (int n = 0; n < 4; n++) acc[m][n] = 0.f;

    for (int f0 = 0; f0 < F; f0 += 16) {
        float4 xv = *(const float4*)&X[(size_t)(i0 + r) * F + f0 + kg * 4];
        Xs[kg * 4 + 0][r] = xv.x;
        Xs[kg * 4 + 1][r] = xv.y;
        Xs[kg * 4 + 2][r] = xv.z;
        Xs[kg * 4 + 3][r] = xv.w;
        const float* wp = &W[(size_t)(nb + o) * F + f0 + kh * 8];
        float4 w0 = *(const float4*)(wp + 0);
        float4 w1 = *(const float4*)(wp + 4);
        Ws[kh * 8 + 0][o] = w0.x;  Ws[kh * 8 + 1][o] = w0.y;
        Ws[kh * 8 + 2][o] = w0.z;  Ws[kh * 8 + 3][o] = w0.w;
        Ws[kh * 8 + 4][o] = w1.x;  Ws[kh * 8 + 5][o] = w1.y;
        Ws[kh * 8 + 6][o] = w1.z;  Ws[kh * 8 + 7][o] = w1.w;
        __syncthreads();
#pragma unroll
        for (int kk = 0; kk < 16; kk++) {
            float av[8], bv[4];
            *(float4*)(av + 0) = *(const float4*)&Xs[kk][ty * 8 + 0];
            *(float4*)(av + 4) = *(const float4*)&Xs[kk][ty * 8 + 4];
            *(float4*)(bv + 0) = *(const float4*)&Ws[kk][tx * 4];
#pragma unroll
            for (int m = 0; m < 8; m++)
#pragma unroll
                for (int n = 0; n < 4; n++) acc[m][n] += av[m] * bv[n];
        }
        __syncthreads();
    }
#pragma unroll
    for (int m = 0; m < 8; m++) {
        int row = i0 + ty * 8 + m;
        *(float4*)&g_Wh[(size_t)row * F + nb + tx * 4] =
            make_float4(acc[m][0], acc[m][1], acc[m][2], acc[m][3]);
    }
}

// ---------------- K1b: pack Wh -> fp16 B-fragment order ----------------
__global__ void __launch_bounds__(256) k1b_pack() {
    __shared__ float sm[32][33];
    const int j0 = blockIdx.x * 32;
    const int n0 = blockIdx.y * 32;
    const int x = threadIdx.x, y = threadIdx.y;   // 32 x 8
#pragma unroll
    for (int q = 0; q < 4; q++)
        sm[y + q * 8][x] = g_Wh[(size_t)(j0 + y + q * 8) * F + n0 + x];
    __syncthreads();
    const int pi  = x & 15;
    const int nbs = x >> 4;
    const int t   = pi >> 2, ks = (pi >> 1) & 1, hi8 = pi & 1;
    const int jl  = ks * 16 + 2 * t + 8 * hi8;
#pragma unroll
    for (int q = 0; q < 2; q++) {
        int nl = y + nbs * 8 + q * 16;
        __half2 h = __floats2half2_rn(sm[jl][nl], sm[jl + 1][nl]);
        g_WhBh[(size_t)(j0 >> 5) * (F * 16) + (size_t)(n0 + nl) * 16 + pi] =
            *(const uint32_t*)&h;
    }
}

// ---------------- K2: scores ----------------
__global__ void __launch_bounds__(256) k2_scores(const float* __restrict__ r) {
    const int gwarp = (blockIdx.x * blockDim.x + threadIdx.x) >> 5;
    const int lane  = threadIdx.x & 31;
    if (gwarp >= NN) return;
    const float* row = &g_Wh[(size_t)gwarp * F];
    float ss = 0.f, sd = 0.f;
#pragma unroll
    for (int q = 0; q < 8; q++) {
        int k = lane + q * 32;
        float v = row[k];
        ss += v * __ldg(&r[k]);
        sd += v * __ldg(&r[F + k]);
    }
#pragma unroll
    for (int o = 16; o > 0; o >>= 1) {
        ss += __shfl_xor_sync(0xffffffffu, ss, o);
        sd += __shfl_xor_sync(0xffffffffu, sd, o);
    }
    if (lane == 0) {
        g_ssrc[gwarp] = ss;
        g_sdst[gwarp] = sd;
    }
}

// ---------------- K3a: partial max of sdst (32 blocks) ----------------
__global__ void __launch_bounds__(256) k3a_pmax() {
    __shared__ float red[256];
    const int t = threadIdx.x;
    red[t] = g_sdst[blockIdx.x * 256 + t];
    __syncthreads();
    for (int s = 128; s > 0; s >>= 1) {
        if (t < s) red[t] = fmaxf(red[t], red[t + s]);
        __syncthreads();
    }
    if (t == 0) g_pmax[blockIdx.x] = red[0];
}

// ---------------- K3b: finish max + stable exp tables ----------------
__global__ void __launch_bounds__(256) k3b_tables() {
    __shared__ float Msh;
    const int t = threadIdx.x;
    if (t < 32) {
        float m = g_pmax[t];
#pragma unroll
        for (int o = 16; o > 0; o >>= 1) m = fmaxf(m, __shfl_xor_sync(0xffffffffu, m, o));
        if (t == 0) Msh = m;
    }
    __syncthreads();
    const float M = Msh;
    const int i = blockIdx.x * 256 + t;
    const float sd = g_sdst[i];
    const float si = g_ssrc[i];
    g_E0[i] = expf(sd - M);
    g_E1[i] = expf(ALPHA_C * (sd - M));
    float u  = si + M;
    float mi = (u >= 0.f) ? u : ALPHA_C * u;
    g_c0[i] = expf(u - mi);
    g_c1[i] = expf(ALPHA_C * u - mi);
}

// ---------------- K4: fp16 mma, 3-stage B pipeline, builder overlap ----------------
// smem: B 3 x 16384 @0 ; fragA 2 x 4096 @49152 ; zsh 512f @57344 ; zinv 64f @59392
#define BBUF     16384
#define FRAG_OFF 49152
#define FRAGBUF  4096
#define ZSH_OFF  57344
#define ZINV_OFF 59392
#define K4_SMEM  59648
#define NCHUNK   (NN / 32)

__global__ void __launch_bounds__(512) k4_mma(const int* __restrict__ A,
                                              float* __restrict__ out) {
    extern __shared__ char smem[];
    const int tid  = threadIdx.x, lane = tid & 31, warp = tid >> 5;
    const int i0 = blockIdx.x * 64;
    const int g = lane >> 2, t = lane & 3;
    const int my = warp >> 2, wx = warp & 3;

    // ---- builder mapping: row r, 4 j's at offset jo within each 32-chunk ----
    const int r  = tid >> 3;
    const int jo = (tid & 7) * 4;
    const float c0 = g_c0[i0 + r];
    const float c1 = g_c1[i0 + r];
    const int4* arow = (const int4*)(A + (size_t)(i0 + r) * NN) + (jo >> 2);
    const int ks_b = jo >> 4, kk = jo & 15;
    const int tA = (kk & 7) >> 1, hi = kk >> 3;
    char* fb0 = smem + FRAG_OFF +
                ((((r >> 4) * 2 + ks_b) * 32 + (r & 7) * 4 + tA) * 16 + hi * 8 + ((r >> 3) & 1) * 4);
    float zp = 0.f;

    // ---- B loader mapping ----
    const uint32_t* bsrc = g_WhBh + (size_t)(tid >> 1) * 16 + (size_t)(tid & 1) * 8;
    const uint32_t bdst = (uint32_t)__cvta_generic_to_shared(smem) + (tid >> 1) * 64 + (tid & 1) * 32;

    float acc[8][4];
#pragma unroll
    for (int u = 0; u < 8; u++)
#pragma unroll
        for (int q = 0; q < 4; q++) acc[u][q] = 0.f;

#define BUILD_CHUNK(E0V, E1V, MASK, FBUF) do {                                 \
        float w0 = fmaxf(c0 * (E0V).x, c1 * (E1V).x);                          \
        float w1 = fmaxf(c0 * (E0V).y, c1 * (E1V).y);                          \
        float w2 = fmaxf(c0 * (E0V).z, c1 * (E1V).z);                          \
        float w3 = fmaxf(c0 * (E0V).w, c1 * (E1V).w);                          \
        __half2 p0 = __floats2half2_rn(w0, w1);                                \
        __half2 p1 = __floats2half2_rn(w2, w3);                                \
        uint32_t m0 = ((MASK).x ? 0x0000FFFFu : 0u) | ((MASK).y ? 0xFFFF0000u : 0u); \
        uint32_t m1 = ((MASK).z ? 0x0000FFFFu : 0u) | ((MASK).w ? 0xFFFF0000u : 0u); \
        uint32_t b0 = (*(const uint32_t*)&p0) & m0;                            \
        uint32_t b1 = (*(const uint32_t*)&p1) & m1;                            \
        char* fb = fb0 + (FBUF) * FRAGBUF;                                     \
        *(uint32_t*)(fb)      = b0;                                            \
        *(uint32_t*)(fb + 16) = b1;                                            \
        float2 z0 = __half22float2(*(const __half2*)&b0);                      \
        float2 z1 = __half22float2(*(const __half2*)&b1);                      \
        zp += (z0.x + z0.y) + (z1.x + z1.y);                                   \
    } while (0)

    // ---- prologue: build chunk 0 -> frag 0, issue B0 -> buf 0, prefetch next ----
    {
        int4   a0 = __ldg(arow);
        float4 e0 = *(const float4*)(g_E0 + jo);
        float4 e1 = *(const float4*)(g_E1 + jo);
        BUILD_CHUNK(e0, e1, a0, 0);
        asm volatile("cp.async.cg.shared.global [%0], [%1], 16;" :: "r"(bdst), "l"(bsrc));
        asm volatile("cp.async.cg.shared.global [%0], [%1], 16;" :: "r"(bdst + 16), "l"(bsrc + 4));
        asm volatile("cp.async.commit_group;");
    }
    int4   cA  = __ldg(arow + 8);
    float4 pe0 = *(const float4*)(g_E0 + 32 + jo);
    float4 pe1 = *(const float4*)(g_E1 + 32 + jo);

    int bcur = 0;   // B buffer of current chunk
    for (int it = 0; it < NCHUNK; ++it) {
        const int f = it & 1;
        const int bnext = (bcur == 2) ? 0 : bcur + 1;

        // ---- issue B(it+1) early -> slack = full iteration ----
        if (it < NCHUNK - 1) {
            const uint32_t* src = bsrc + (size_t)(it + 1) * 4096;
            uint32_t dst = bdst + bnext * BBUF;
            asm volatile("cp.async.cg.shared.global [%0], [%1], 16;" :: "r"(dst), "l"(src));
            asm volatile("cp.async.cg.shared.global [%0], [%1], 16;" :: "r"(dst + 16), "l"(src + 4));
            asm volatile("cp.async.commit_group;");
            asm volatile("cp.async.wait_group 1;");
        } else {
            asm volatile("cp.async.wait_group 0;");
        }
        __syncthreads();

        // ---- MMA chunk it ----
        {
            const char* bb = smem + bcur * BBUF;
            const char* fa = smem + FRAG_OFF + f * FRAGBUF;
            uint4 aq0 = *(const uint4*)(fa + ((my * 2 + 0) * 32 + lane) * 16);
            uint4 aq1 = *(const uint4*)(fa + ((my * 2 + 1) * 32 + lane) * 16);
#pragma unroll
            for (int u = 0; u < 8; u++) {
                uint4 bq = *(const uint4*)(bb + (wx * 64 + u * 8 + g) * 64 + t * 16);
                mma_f16(acc[u], (const uint32_t*)&aq0, bq.x, bq.y);
                mma_f16(acc[u], (const uint32_t*)&aq1, bq.z, bq.w);
            }
        }

        // ---- build chunk it+1 from prefetched regs; prefetch it+2 ----
        if (it < NCHUNK - 1) {
            BUILD_CHUNK(pe0, pe1, cA, f ^ 1);
            if (it < NCHUNK - 2) {
                cA  = __ldg(arow + (it + 2) * 8);
                pe0 = *(const float4*)(g_E0 + (it + 2) * 32 + jo);
                pe1 = *(const float4*)(g_E1 + (it + 2) * 32 + jo);
            }
        }
        bcur = bnext;
    }
#undef BUILD_CHUNK

    // ---- Z reduce (deterministic) ----
    float* zsh  = (float*)(smem + ZSH_OFF);
    float* zinv = (float*)(smem + ZINV_OFF);
    __syncthreads();
    zsh[tid] = zp;
    __syncthreads();
    if (tid < 64) {
        const float* p = zsh + tid * 8;
        float z = ((p[0] + p[1]) + (p[2] + p[3])) + ((p[4] + p[5]) + (p[6] + p[7]));
        zinv[tid] = 1.0f / z;
    }
    __syncthreads();

    // ---- epilogue: /Z, exact GELU, store ----
    const int rr = my * 16 + g;
    const float zi0 = zinv[rr];
    const float zi1 = zinv[rr + 8];
#pragma unroll
    for (int u = 0; u < 8; u++) {
        int col = wx * 64 + u * 8 + t * 2;
        float x0 = acc[u][0] * zi0;
        float x1 = acc[u][1] * zi0;
        float x2 = acc[u][2] * zi1;
        float x3 = acc[u][3] * zi1;
        float g0 = 0.5f * x0 * (1.0f + erff(x0 * 0.70710678118654752f));
        float g1 = 0.5f * x1 * (1.0f + erff(x1 * 0.70710678118654752f));
        float g2 = 0.5f * x2 * (1.0f + erff(x2 * 0.70710678118654752f));
        float g3 = 0.5f * x3 * (1.0f + erff(x3 * 0.70710678118654752f));
        *(float2*)&out[(size_t)(i0 + rr) * F + col]     = make_float2(g0, g1);
        *(float2*)&out[(size_t)(i0 + rr + 8) * F + col] = make_float2(g2, g3);
    }
}

// ---------------- launch ----------------
extern "C" void kernel_launch(void* const* d_in, const int* in_sizes, int n_in,
                              void* d_out, int out_size) {
    (void)in_sizes; (void)n_in; (void)out_size;
    const float* X = (const float*)d_in[0];
    const int*   A = (const int*)d_in[1];
    const float* W = (const float*)d_in[2];
    const float* r = (const float*)d_in[3];
    float* out = (float*)d_out;

    cudaFuncSetAttribute(k4_mma, cudaFuncAttributeMaxDynamicSharedMemorySize, K4_SMEM);

    k1_wh<<<dim3(NN / 64, 2), 256>>>(X, W);
    k1b_pack<<<dim3(NN / 32, F / 32), dim3(32, 8)>>>();
    k2_scores<<<(NN * 32) / 256, 256>>>(r);
    k3a_pmax<<<32, 256>>>();
    k3b_tables<<<NN / 256, 256>>>();
    k4_mma<<<NN / 64, 512, K4_SMEM>>>(A, out);
}

// round 8
// speedup vs baseline: 1.5101x; 1.3030x over previous
#include <cuda_runtime.h>
#include <cuda_fp16.h>
#include <math.h>
#include <stdint.h>

#define NN 8192
#define F  256
#define ALPHA_C 0.2f

// ---------------- scratch ----------------
__device__ float    g_Wh[NN * F];              // fp32 Wh [i][n]
__device__ uint32_t g_WhBh[NN / 32 * F * 16];  // fp16 Wh, B-fragment order [chunk][n][pi]
__device__ float    g_ssrc[NN];
__device__ float    g_sdst[NN];
__device__ float    g_E0[NN];
__device__ float    g_E1[NN];
__device__ float    g_c0[NN];
__device__ float    g_c1[NN];
__device__ unsigned g_gmax_enc;                // order-encoded float max (idempotent across replays)

// ---------------- helpers ----------------
__device__ __forceinline__ void mma_f16(float* d, const uint32_t* a, uint32_t b0, uint32_t b1) {
    asm volatile(
        "mma.sync.aligned.m16n8k16.row.col.f32.f16.f16.f32 "
        "{%0,%1,%2,%3}, {%4,%5,%6,%7}, {%8,%9}, {%0,%1,%2,%3};\n"
        : "+f"(d[0]), "+f"(d[1]), "+f"(d[2]), "+f"(d[3])
        : "r"(a[0]), "r"(a[1]), "r"(a[2]), "r"(a[3]), "r"(b0), "r"(b1));
}
__device__ __forceinline__ unsigned fenc(float f) {
    unsigned b = __float_as_uint(f);
    return (b & 0x80000000u) ? ~b : (b | 0x80000000u);
}
__device__ __forceinline__ float fdec(unsigned e) {
    unsigned b = (e & 0x80000000u) ? (e & 0x7FFFFFFFu) : ~e;
    return __uint_as_float(b);
}

// ---------------- K1: Wh = X @ W^T (fp32) + fused fp16 B-fragment pack ----------------
__global__ void __launch_bounds__(256) k1_wh(const float* __restrict__ X,
                                             const float* __restrict__ W) {
    __shared__ float Xs[16][64];
    __shared__ float Ws[16][128];
    const int tid = threadIdx.x;
    const int i0  = blockIdx.x * 64;
    const int nb  = blockIdx.y * 128;
    const int ty  = tid >> 5, tx = tid & 31;
    const int r   = tid & 63, kg = tid >> 6;
    const int o   = tid & 127, kh = tid >> 7;

    float acc[8][4];
#pragma unroll
    for (int m = 0; m < 8; m++)
#pragma unroll
        for (int n = 0; n < 4; n++) acc[m][n] = 0.f;

    for (int f0 = 0; f0 < F; f0 += 16) {
        float4 xv = *(const float4*)&X[(size_t)(i0 + r) * F + f0 + kg * 4];
        Xs[kg * 4 + 0][r] = xv.x;
        Xs[kg * 4 + 1][r] = xv.y;
        Xs[kg * 4 + 2][r] = xv.z;
        Xs[kg * 4 + 3][r] = xv.w;
        const float* wp = &W[(size_t)(nb + o) * F + f0 + kh * 8];
        float4 w0 = *(const float4*)(wp + 0);
        float4 w1 = *(const float4*)(wp + 4);
        Ws[kh * 8 + 0][o] = w0.x;  Ws[kh * 8 + 1][o] = w0.y;
        Ws[kh * 8 + 2][o] = w0.z;  Ws[kh * 8 + 3][o] = w0.w;
        Ws[kh * 8 + 4][o] = w1.x;  Ws[kh * 8 + 5][o] = w1.y;
        Ws[kh * 8 + 6][o] = w1.z;  Ws[kh * 8 + 7][o] = w1.w;
        __syncthreads();
#pragma unroll
        for (int kk = 0; kk < 16; kk++) {
            float av[8], bv[4];
            *(float4*)(av + 0) = *(const float4*)&Xs[kk][ty * 8 + 0];
            *(float4*)(av + 4) = *(const float4*)&Xs[kk][ty * 8 + 4];
            *(float4*)(bv + 0) = *(const float4*)&Ws[kk][tx * 4];
#pragma unroll
            for (int m = 0; m < 8; m++)
#pragma unroll
                for (int n = 0; n < 4; n++) acc[m][n] += av[m] * bv[n];
        }
        __syncthreads();
    }
#pragma unroll
    for (int m = 0; m < 8; m++) {
        int row = i0 + ty * 8 + m;
        *(float4*)&g_Wh[(size_t)row * F + nb + tx * 4] =
            make_float4(acc[m][0], acc[m][1], acc[m][2], acc[m][3]);
    }
    // fused pack: rows j = i0+ty*8+m are this thread's accs; pairs (m, m+1)
    {
        const int chunk = (i0 + ty * 8) >> 5;
        const int jb    = (i0 + ty * 8) & 31;
        uint32_t* dst = g_WhBh + (size_t)chunk * (F * 16);
#pragma unroll
        for (int mp = 0; mp < 4; mp++) {
            int jl = jb + 2 * mp;
            int pi = ((jl & 7) >> 1) * 4 + ((jl >> 4) & 1) * 2 + ((jl >> 3) & 1);
#pragma unroll
            for (int c = 0; c < 4; c++) {
                __half2 h = __floats2half2_rn(acc[2 * mp][c], acc[2 * mp + 1][c]);
                dst[(size_t)(nb + tx * 4 + c) * 16 + pi] = *(const uint32_t*)&h;
            }
        }
    }
}

// ---------------- K2: scores + fused global max (encoded atomicMax) ----------------
__global__ void __launch_bounds__(256) k2_scores(const float* __restrict__ r) {
    const int gwarp = (blockIdx.x * blockDim.x + threadIdx.x) >> 5;
    const int lane  = threadIdx.x & 31;
    if (gwarp >= NN) return;
    const float* row = &g_Wh[(size_t)gwarp * F];
    float ss = 0.f, sd = 0.f;
#pragma unroll
    for (int q = 0; q < 8; q++) {
        int k = lane + q * 32;
        float v = row[k];
        ss += v * __ldg(&r[k]);
        sd += v * __ldg(&r[F + k]);
    }
#pragma unroll
    for (int o = 16; o > 0; o >>= 1) {
        ss += __shfl_xor_sync(0xffffffffu, ss, o);
        sd += __shfl_xor_sync(0xffffffffu, sd, o);
    }
    if (lane == 0) {
        g_ssrc[gwarp] = ss;
        g_sdst[gwarp] = sd;
        atomicMax(&g_gmax_enc, fenc(sd));
    }
}

// ---------------- K3b: stable exp tables ----------------
__global__ void __launch_bounds__(256) k3b_tables() {
    const int i = blockIdx.x * 256 + threadIdx.x;
    const float M  = fdec(g_gmax_enc);
    const float sd = g_sdst[i];
    const float si = g_ssrc[i];
    g_E0[i] = expf(sd - M);
    g_E1[i] = expf(ALPHA_C * (sd - M));
    float u  = si + M;
    float mi = (u >= 0.f) ? u : ALPHA_C * u;
    g_c0[i] = expf(u - mi);
    g_c1[i] = expf(ALPHA_C * u - mi);
}

// ---------------- K4: fp16 mma, BK=64, R4 pipeline structure ----------------
// smem: B 2 x 32768 @0 ; fragA 2 x 8192 @65536 ; zsh 512f @81920 ; zinv 64f @83968
#define BBUF     32768
#define FRAG_OFF 65536
#define FRAGBUF  8192
#define ZSH_OFF  81920
#define ZINV_OFF 83968
#define K4_SMEM  84224
#define NCHUNK   (NN / 64)

__global__ void __launch_bounds__(512) k4_mma(const int* __restrict__ A,
                                              float* __restrict__ out) {
    extern __shared__ char smem[];
    const int tid  = threadIdx.x, lane = tid & 31, warp = tid >> 5;
    const int i0 = blockIdx.x * 64;
    const int g = lane >> 2, t = lane & 3;
    const int my = warp >> 2, wx = warp & 3;

    // ---- builder mapping: row r, 8 j's at offset jo within each 64-chunk ----
    const int r  = tid >> 3;
    const int jo = (tid & 7) * 8;
    const float c0 = g_c0[i0 + r];
    const float c1 = g_c1[i0 + r];
    const int4* arow = (const int4*)(A + (size_t)(i0 + r) * NN) + (jo >> 2);
    const int ks = jo >> 4;              // 0..3
    const int hi = (jo >> 3) & 1;
    char* fb0 = smem + FRAG_OFF +
                ((((r >> 4) * 4 + ks) * 32 + (r & 7) * 4) * 16 + hi * 8 + ((r >> 3) & 1) * 4);
    float zp = 0.f;

    // ---- B loader mapping: n = tid>>1, half = tid&1 ----
    const uint32_t* bsrc = g_WhBh + (size_t)(tid >> 1) * 16 + (size_t)(tid & 1) * 8;
    const uint32_t bdst = (uint32_t)__cvta_generic_to_shared(smem) + (tid >> 1) * 64 + (tid & 1) * 32;

    float acc[8][4];
#pragma unroll
    for (int u = 0; u < 8; u++)
#pragma unroll
        for (int q = 0; q < 4; q++) acc[u][q] = 0.f;

#define BUILD_CHUNK(CIDX, MA0, MA1, SBUF) do {                                 \
        const int jj = (CIDX) * 64 + jo;                                       \
        float4 e0a = *(const float4*)(g_E0 + jj);                              \
        float4 e0b = *(const float4*)(g_E0 + jj + 4);                          \
        float4 e1a = *(const float4*)(g_E1 + jj);                              \
        float4 e1b = *(const float4*)(g_E1 + jj + 4);                          \
        float w0 = fmaxf(c0 * e0a.x, c1 * e1a.x);                              \
        float w1 = fmaxf(c0 * e0a.y, c1 * e1a.y);                              \
        float w2 = fmaxf(c0 * e0a.z, c1 * e1a.z);                              \
        float w3 = fmaxf(c0 * e0a.w, c1 * e1a.w);                              \
        float w4 = fmaxf(c0 * e0b.x, c1 * e1b.x);                              \
        float w5 = fmaxf(c0 * e0b.y, c1 * e1b.y);                              \
        float w6 = fmaxf(c0 * e0b.z, c1 * e1b.z);                              \
        float w7 = fmaxf(c0 * e0b.w, c1 * e1b.w);                              \
        __half2 p0 = __floats2half2_rn(w0, w1);                                \
        __half2 p1 = __floats2half2_rn(w2, w3);                                \
        __half2 p2 = __floats2half2_rn(w4, w5);                                \
        __half2 p3 = __floats2half2_rn(w6, w7);                                \
        uint32_t q0 = (*(const uint32_t*)&p0) &                                \
            (((MA0).x ? 0x0000FFFFu : 0u) | ((MA0).y ? 0xFFFF0000u : 0u));     \
        uint32_t q1 = (*(const uint32_t*)&p1) &                                \
            (((MA0).z ? 0x0000FFFFu : 0u) | ((MA0).w ? 0xFFFF0000u : 0u));     \
        uint32_t q2 = (*(const uint32_t*)&p2) &                                \
            (((MA1).x ? 0x0000FFFFu : 0u) | ((MA1).y ? 0xFFFF0000u : 0u));     \
        uint32_t q3 = (*(const uint32_t*)&p3) &                                \
            (((MA1).z ? 0x0000FFFFu : 0u) | ((MA1).w ? 0xFFFF0000u : 0u));     \
        char* fb = fb0 + (SBUF) * FRAGBUF;                                     \
        *(uint32_t*)(fb)      = q0;                                            \
        *(uint32_t*)(fb + 16) = q1;                                            \
        *(uint32_t*)(fb + 32) = q2;                                            \
        *(uint32_t*)(fb + 48) = q3;                                            \
        float2 z0 = __half22float2(*(const __half2*)&q0);                      \
        float2 z1 = __half22float2(*(const __half2*)&q1);                      \
        float2 z2 = __half22float2(*(const __half2*)&q2);                      \
        float2 z3 = __half22float2(*(const __half2*)&q3);                      \
        zp += ((z0.x + z0.y) + (z1.x + z1.y)) + ((z2.x + z2.y) + (z3.x + z3.y)); \
    } while (0)

    // ---- prologue: A-mask chunk0 + issue B0 ----
    int4 cA0 = __ldg(arow + 0);
    int4 cA1 = __ldg(arow + 1);
    {
        asm volatile("cp.async.cg.shared.global [%0], [%1], 16;" :: "r"(bdst), "l"(bsrc));
        asm volatile("cp.async.cg.shared.global [%0], [%1], 16;" :: "r"(bdst + 16), "l"(bsrc + 4));
        asm volatile("cp.async.cg.shared.global [%0], [%1], 16;" :: "r"(bdst + BBUF / 2), "l"(bsrc + 4096));
        asm volatile("cp.async.cg.shared.global [%0], [%1], 16;" :: "r"(bdst + BBUF / 2 + 16), "l"(bsrc + 4100));
        asm volatile("cp.async.commit_group;");
    }

    for (int it = 0; it < NCHUNK; ++it) {
        const int s = it & 1;

        // prefetch next A-mask
        int4 nA0, nA1;
        if (it < NCHUNK - 1) {
            nA0 = __ldg(arow + (it + 1) * 16);
            nA1 = __ldg(arow + (it + 1) * 16 + 1);
        }

        // build chunk it -> frag buf s
        BUILD_CHUNK(it, cA0, cA1, s);

        asm volatile("cp.async.wait_group 0;");
        __syncthreads();

        // issue B(it+1) -> buf s^1 (waited after next build + this MMA)
        if (it < NCHUNK - 1) {
            const uint32_t* src = bsrc + (size_t)(it + 1) * 8192;
            uint32_t dst = bdst + (s ^ 1) * BBUF;
            asm volatile("cp.async.cg.shared.global [%0], [%1], 16;" :: "r"(dst), "l"(src));
            asm volatile("cp.async.cg.shared.global [%0], [%1], 16;" :: "r"(dst + 16), "l"(src + 4));
            asm volatile("cp.async.cg.shared.global [%0], [%1], 16;" :: "r"(dst + BBUF / 2), "l"(src + 4096));
            asm volatile("cp.async.cg.shared.global [%0], [%1], 16;" :: "r"(dst + BBUF / 2 + 16), "l"(src + 4100));
            asm volatile("cp.async.commit_group;");
        }

        // ---- MMA chunk it: 4 k-steps of 16 ----
        {
            const char* bb = smem + s * BBUF;
            const char* fa = smem + FRAG_OFF + s * FRAGBUF;
            uint4 aq0 = *(const uint4*)(fa + ((my * 4 + 0) * 32 + lane) * 16);
            uint4 aq1 = *(const uint4*)(fa + ((my * 4 + 1) * 32 + lane) * 16);
            uint4 aq2 = *(const uint4*)(fa + ((my * 4 + 2) * 32 + lane) * 16);
            uint4 aq3 = *(const uint4*)(fa + ((my * 4 + 3) * 32 + lane) * 16);
#pragma unroll
            for (int u = 0; u < 8; u++) {
                const int boff = (wx * 64 + u * 8 + g) * 64 + t * 16;
                uint4 bq0 = *(const uint4*)(bb + boff);
                uint4 bq1 = *(const uint4*)(bb + BBUF / 2 + boff);
                mma_f16(acc[u], (const uint32_t*)&aq0, bq0.x, bq0.y);
                mma_f16(acc[u], (const uint32_t*)&aq1, bq0.z, bq0.w);
                mma_f16(acc[u], (const uint32_t*)&aq2, bq1.x, bq1.y);
                mma_f16(acc[u], (const uint32_t*)&aq3, bq1.z, bq1.w);
            }
        }

        cA0 = nA0;
        cA1 = nA1;
    }
#undef BUILD_CHUNK

    // ---- Z reduce (deterministic) ----
    float* zsh  = (float*)(smem + ZSH_OFF);
    float* zinv = (float*)(smem + ZINV_OFF);
    __syncthreads();
    zsh[tid] = zp;
    __syncthreads();
    if (tid < 64) {
        const float* p = zsh + tid * 8;
        float z = ((p[0] + p[1]) + (p[2] + p[3])) + ((p[4] + p[5]) + (p[6] + p[7]));
        zinv[tid] = 1.0f / z;
    }
    __syncthreads();

    // ---- epilogue: /Z, exact GELU, store ----
    const int rr = my * 16 + g;
    const float zi0 = zinv[rr];
    const float zi1 = zinv[rr + 8];
#pragma unroll
    for (int u = 0; u < 8; u++) {
        int col = wx * 64 + u * 8 + t * 2;
        float x0 = acc[u][0] * zi0;
        float x1 = acc[u][1] * zi0;
        float x2 = acc[u][2] * zi1;
        float x3 = acc[u][3] * zi1;
        float g0 = 0.5f * x0 * (1.0f + erff(x0 * 0.70710678118654752f));
        float g1 = 0.5f * x1 * (1.0f + erff(x1 * 0.70710678118654752f));
        float g2 = 0.5f * x2 * (1.0f + erff(x2 * 0.70710678118654752f));
        float g3 = 0.5f * x3 * (1.0f + erff(x3 * 0.70710678118654752f));
        *(float2*)&out[(size_t)(i0 + rr) * F + col]     = make_float2(g0, g1);
        *(float2*)&out[(size_t)(i0 + rr + 8) * F + col] = make_float2(g2, g3);
    }
}

// ---------------- launch ----------------
extern "C" void kernel_launch(void* const* d_in, const int* in_sizes, int n_in,
                              void* d_out, int out_size) {
    (void)in_sizes; (void)n_in; (void)out_size;
    const float* X = (const float*)d_in[0];
    const int*   A = (const int*)d_in[1];
    const float* W = (const float*)d_in[2];
    const float* r = (const float*)d_in[3];
    float* out = (float*)d_out;

    cudaFuncSetAttribute(k4_mma, cudaFuncAttributeMaxDynamicSharedMemorySize, K4_SMEM);

    k1_wh<<<dim3(NN / 64, 2), 256>>>(X, W);
    k2_scores<<<(NN * 32) / 256, 256>>>(r);
    k3b_tables<<<NN / 256, 256>>>();
    k4_mma<<<NN / 64, 512, K4_SMEM>>>(A, out);
}